// round 16
// baseline (speedup 1.0000x reference)
#include <cuda_runtime.h>
#include <cuda_fp16.h>
#include <math.h>
#include <stdint.h>

#define S_LEN 2048
#define HDIM  2048
#define NB    2
#define NH    16
#define DH    128
#define MROWS (NB * S_LEN)   // 4096

__device__ __half g_Q[MROWS * HDIM];
__device__ __half g_K[MROWS * HDIM];
__device__ __half g_V[MROWS * HDIM];
__device__ __half g_C[MROWS * HDIM];
__device__ __half g_X[MROWS * HDIM];
__device__ __half g_Wq[HDIM * HDIM];         // pre-scaled 1/sqrt(dh)
__device__ __half g_Wk[HDIM * HDIM];
__device__ __half g_Wv[HDIM * HDIM];
__device__ __half g_Wo[HDIM * HDIM];

// ---------------------------------------------------------------------------
// fp16 MMA m16n8k16 + ldmatrix helpers
// ---------------------------------------------------------------------------
__device__ __forceinline__ void mma_f16(float* c, uint32_t a0, uint32_t a1,
                                        uint32_t a2, uint32_t a3,
                                        uint32_t b0, uint32_t b1)
{
    asm("mma.sync.aligned.m16n8k16.row.col.f32.f16.f16.f32 "
        "{%0,%1,%2,%3}, {%4,%5,%6,%7}, {%8,%9}, {%0,%1,%2,%3};"
        : "+f"(c[0]), "+f"(c[1]), "+f"(c[2]), "+f"(c[3])
        : "r"(a0), "r"(a1), "r"(a2), "r"(a3), "r"(b0), "r"(b1));
}

__device__ __forceinline__ void ldsm_x4(uint32_t* r, uint32_t addr)
{
    asm volatile("ldmatrix.sync.aligned.m8n8.x4.shared.b16 {%0,%1,%2,%3}, [%4];"
                 : "=r"(r[0]), "=r"(r[1]), "=r"(r[2]), "=r"(r[3]) : "r"(addr));
}

__device__ __forceinline__ void ldsm_x4_t(uint32_t* r, uint32_t addr)
{
    asm volatile(
        "ldmatrix.sync.aligned.m8n8.x4.trans.shared.b16 {%0,%1,%2,%3}, [%4];"
        : "=r"(r[0]), "=r"(r[1]), "=r"(r[2]), "=r"(r[3]) : "r"(addr));
}

__device__ __forceinline__ uint32_t pack_h2(float lo, float hi)
{
    __half2 h = __floats2half2_rn(lo, hi);
    return *(uint32_t*)&h;
}

__device__ __forceinline__ void cp_async16(uint32_t saddr, const void* g)
{
    asm volatile("cp.async.cg.shared.global [%0], [%1], 16;"
                 :: "r"(saddr), "l"(g));
}
#define CP_COMMIT() asm volatile("cp.async.commit_group;")
#define CP_WAIT(N)  asm volatile("cp.async.wait_group %0;" :: "n"(N))

// ---------------------------------------------------------------------------
// fp32 -> fp16 pre-rounding copy: y=0 -> X, y=1..4 -> Wq,Wk,Wv,Wo (fused)
// ---------------------------------------------------------------------------
__global__ void cvt_all_kernel(const float* __restrict__ X,
                               const float* __restrict__ Wq,
                               const float* __restrict__ Wk,
                               const float* __restrict__ Wv,
                               const float* __restrict__ Wo,
                               __half* __restrict__ dX,
                               __half* __restrict__ dWq,
                               __half* __restrict__ dWk,
                               __half* __restrict__ dWv,
                               __half* __restrict__ dWo,
                               int nx8, int nw8, float rs)
{
    int i = blockIdx.x * 256 + threadIdx.x;
    int y = blockIdx.y;
    int n8 = (y == 0) ? nx8 : nw8;
    if (i >= n8) return;
    const float* src = (y == 0) ? X : (y == 1) ? Wq : (y == 2) ? Wk
                     : (y == 3) ? Wv : Wo;
    __half* dst = (y == 0) ? dX : (y == 1) ? dWq : (y == 2) ? dWk
                : (y == 3) ? dWv : dWo;
    float scale = (y == 1) ? rs : 1.f;
    float4 v0 = ((const float4*)src)[2 * i];
    float4 v1 = ((const float4*)src)[2 * i + 1];
    uint4 o;
    o.x = pack_h2(v0.x * scale, v0.y * scale);
    o.y = pack_h2(v0.z * scale, v0.w * scale);
    o.z = pack_h2(v1.x * scale, v1.y * scale);
    o.w = pack_h2(v1.z * scale, v1.w * scale);
    ((uint4*)dst)[i] = o;
}

// ---------------------------------------------------------------------------
// fp16 GEMM: CTA 128x128, 4 warps, BK=32, ldmatrix frags, rows padded 80B.
// v8: THREE cp.async stages (60 KB/CTA) + __launch_bounds__(128,3) ->
// 3 CTAs/SM (12 warps/SM) for wave-quantization and issue coverage.
// ---------------------------------------------------------------------------
#define GK 2048
#define STAGE_B 10240                     // 128 rows * 80 bytes
#define NSTG 3
#define GEMM_SMEM_BYTES (NSTG * 2 * STAGE_B) // 61440

template <bool TOHALF, bool HASBIAS>
__device__ __forceinline__ void gemm_f16_body(const __half* __restrict__ A,
                                              const __half* __restrict__ B,
                                              const float* __restrict__ bias,
                                              void* __restrict__ Cout)
{
    extern __shared__ __align__(16) char smem[];
    uint32_t sbase = (uint32_t)__cvta_generic_to_shared(smem);

    const int tid    = threadIdx.x;
    const int lane   = tid & 31;
    const int wid    = tid >> 5;
    const int warp_m = wid >> 1;
    const int warp_n = wid & 1;
    const int g      = lane >> 2;
    const int t      = lane & 3;
    const int bm     = blockIdx.y * 128;
    const int bn     = blockIdx.x * 128;

    const int tr = tid >> 2;
    const int tc = tid & 3;
    const __half* gA = A + (size_t)(bm + tr) * GK + tc * 8;
    const __half* gB = B + (size_t)(bn + tr) * GK + tc * 8;
    const uint32_t dst0 = tr * 80 + tc * 16;

    auto issue = [&](int stage) {
        uint32_t da = sbase + stage * STAGE_B + dst0;
        uint32_t db = da + NSTG * STAGE_B;
#pragma unroll
        for (int it = 0; it < 4; it++)
            cp_async16(da + it * 32 * 80, gA + (size_t)it * 32 * GK);
#pragma unroll
        for (int it = 0; it < 4; it++)
            cp_async16(db + it * 32 * 80, gB + (size_t)it * 32 * GK);
        gA += 32;
        gB += 32;
        CP_COMMIT();
    };

    issue(0);
    issue(1);

    float acc[4][8][4];
#pragma unroll
    for (int mt = 0; mt < 4; mt++)
#pragma unroll
        for (int nt = 0; nt < 8; nt++)
#pragma unroll
            for (int i = 0; i < 4; i++) acc[mt][nt][i] = 0.f;

    const uint32_t aoff =
        ((warp_m * 64 + (lane & 15)) * 40 + (lane >> 4) * 8) * 2;
    const uint32_t boff =
        ((warp_n * 64 + (lane & 7) + (lane >> 4) * 8) * 40 +
         ((lane >> 3) & 1) * 8) * 2;

    const int nk = GK / 32;   // 64
    for (int kt = 0; kt < nk; kt++) {
        if (kt < nk - 1) { CP_WAIT(1); } else { CP_WAIT(0); }
        __syncthreads();
        if (kt + 2 < nk) issue((kt + 2) % NSTG);

        const uint32_t sAst = sbase + (kt % NSTG) * STAGE_B;
        const uint32_t sBst = sAst + NSTG * STAGE_B;

#pragma unroll
        for (int kg = 0; kg < 2; kg++) {
            uint32_t a[4][4], b[4][4];
#pragma unroll
            for (int mt = 0; mt < 4; mt++)
                ldsm_x4(a[mt], sAst + aoff + mt * 1280 + kg * 32);
#pragma unroll
            for (int p = 0; p < 4; p++)
                ldsm_x4(b[p], sBst + boff + p * 1280 + kg * 32);
#pragma unroll
            for (int mt = 0; mt < 4; mt++)
#pragma unroll
                for (int p = 0; p < 4; p++) {
                    mma_f16(acc[mt][2 * p], a[mt][0], a[mt][1], a[mt][2],
                            a[mt][3], b[p][0], b[p][1]);
                    mma_f16(acc[mt][2 * p + 1], a[mt][0], a[mt][1], a[mt][2],
                            a[mt][3], b[p][2], b[p][3]);
                }
        }
    }

#pragma unroll
    for (int mt = 0; mt < 4; mt++) {
        int row = bm + warp_m * 64 + mt * 16 + g;
#pragma unroll
        for (int nt = 0; nt < 8; nt++) {
            int col = bn + warp_n * 64 + nt * 8 + 2 * t;
            if (TOHALF) {
                __half* C = (__half*)Cout;
                *(__half2*)(C + (size_t)row * HDIM + col) =
                    __floats2half2_rn(acc[mt][nt][0], acc[mt][nt][1]);
                *(__half2*)(C + (size_t)(row + 8) * HDIM + col) =
                    __floats2half2_rn(acc[mt][nt][2], acc[mt][nt][3]);
            } else {
                float* C = (float*)Cout;
                float b0 = 0.f, b1 = 0.f;
                if (HASBIAS) { b0 = bias[col]; b1 = bias[col + 1]; }
                *(float2*)(C + (size_t)row * HDIM + col) =
                    make_float2(acc[mt][nt][0] + b0, acc[mt][nt][1] + b1);
                *(float2*)(C + (size_t)(row + 8) * HDIM + col) =
                    make_float2(acc[mt][nt][2] + b0, acc[mt][nt][3] + b1);
            }
        }
    }
}

__global__ void __launch_bounds__(128, 3) qkv_gemm_kernel()
{
    const __half* B = (blockIdx.z == 0) ? g_Wq : (blockIdx.z == 1) ? g_Wk : g_Wv;
    __half* C       = (blockIdx.z == 0) ? g_Q  : (blockIdx.z == 1) ? g_K  : g_V;
    gemm_f16_body<true, false>(g_X, B, nullptr, C);
}

__global__ void __launch_bounds__(128, 3) out_gemm_kernel(
    const float* __restrict__ bo, float* __restrict__ out)
{
    gemm_f16_body<false, true>(g_C, g_Wo, bo, out);
}

// ---------------------------------------------------------------------------
// RoPE in-place on g_Q, g_K — vectorized: 2 adjacent d per thread (half2).
// ---------------------------------------------------------------------------
__global__ void rope_kernel(const int* __restrict__ pos_ids)
{
    int idx = blockIdx.x * 256 + threadIdx.x;
    if (idx >= MROWS * NH * 32) return;
    int d2 = idx & 31;
    int h  = (idx >> 5) & 15;
    int m  = idx >> 9;
    int s  = m & (S_LEN - 1);

    float p = (float)pos_ids[s];
    int d = 2 * d2;
    float th0 = expf(-0.14391156531392624f * (float)d);
    float th1 = expf(-0.14391156531392624f * (float)(d + 1));
    float sn0, cs0, sn1, cs1;
    sincosf(p * th0, &sn0, &cs0);
    sincosf(p * th1, &sn1, &cs1);

    size_t base = (size_t)m * HDIM + h * DH + d;
    float2 q1 = __half22float2(*(__half2*)(g_Q + base));
    float2 q2 = __half22float2(*(__half2*)(g_Q + base + 64));
    *(__half2*)(g_Q + base) =
        __floats2half2_rn(q1.x * cs0 - q2.x * sn0, q1.y * cs1 - q2.y * sn1);
    *(__half2*)(g_Q + base + 64) =
        __floats2half2_rn(q1.x * sn0 + q2.x * cs0, q1.y * sn1 + q2.y * cs1);
    float2 k1 = __half22float2(*(__half2*)(g_K + base));
    float2 k2 = __half22float2(*(__half2*)(g_K + base + 64));
    *(__half2*)(g_K + base) =
        __floats2half2_rn(k1.x * cs0 - k2.x * sn0, k1.y * cs1 - k2.y * sn1);
    *(__half2*)(g_K + base + 64) =
        __floats2half2_rn(k1.x * sn0 + k2.x * cs0, k1.y * sn1 + k2.y * cs1);
}

// ---------------------------------------------------------------------------
// fp16 flash attention (R11-proven): cp.async double-buffered K/V,
// trans-ldmatrix V, TWO barriers per kv-tile.
// ---------------------------------------------------------------------------
#define ASTR 136
#define QB   (128 * ASTR * 2)
#define KVST (64 * ASTR * 2)
#define ATT_SMEM_BYTES (QB + 2 * 2 * KVST)   // 104448

__global__ void __launch_bounds__(256, 2) attn_kernel()
{
    extern __shared__ __align__(16) __half smh[];
    __half* Qs = smh;

    const int tid  = threadIdx.x;
    const int lane = tid & 31;
    const int w    = tid >> 5;
    const int g    = lane >> 2;
    const int t    = lane & 3;
    const int qt   = (gridDim.x - 1) - blockIdx.x;   // heavy tiles first
    const int h    = blockIdx.y;
    const int n    = blockIdx.z;
    const int q0   = qt * 128;

    const size_t rowbase = (size_t)n * S_LEN;
    const size_t hoff    = (size_t)h * DH;

    const uint32_t smb = (uint32_t)__cvta_generic_to_shared(smh);

    const uint32_t qoff =
        smb + ((w * 16 + (lane & 15)) * ASTR + (lane >> 4) * 8) * 2;
    const uint32_t koff =
        (((lane & 7) + (lane >> 4) * 8) * ASTR + ((lane >> 3) & 1) * 8) * 2;
    const uint32_t voff =
        ((lane & 15) * ASTR + (lane >> 4) * 8) * 2;

    const int lr = tid >> 2;
    const int lc = tid & 3;
    auto loadkv = [&](int st, int kt) {
        int k0 = kt * 64;
        uint32_t kb = smb + QB + st * (2 * KVST);
        uint32_t vb = kb + KVST;
#pragma unroll
        for (int it = 0; it < 4; it++) {
            int c = lc * 4 + it;
            size_t gg = (rowbase + k0 + lr) * HDIM + hoff + c * 8;
            cp_async16(kb + (lr * ASTR + c * 8) * 2, g_K + gg);
            cp_async16(vb + (lr * ASTR + c * 8) * 2, g_V + gg);
        }
        CP_COMMIT();
    };

#pragma unroll
    for (int it = 0; it < 8; it++) {
        int id = tid + it * 256;
        int r  = id >> 4;
        int c  = id & 15;
        *(uint4*)&Qs[r * ASTR + c * 8] =
            *(const uint4*)(g_Q + (rowbase + q0 + r) * HDIM + hoff + c * 8);
    }

    float o[16][4];
#pragma unroll
    for (int dd = 0; dd < 16; dd++)
#pragma unroll
        for (int i = 0; i < 4; i++) o[dd][i] = 0.f;
    float m0 = -1e30f, m1 = -1e30f, l0 = 0.f, l1 = 0.f;

    const int row0 = q0 + w * 16 + g;
    const int nkt  = 2 * (qt + 1);

    loadkv(0, 0);

    for (int kt = 0; kt < nkt; kt++) {
        const int st = kt & 1;
        if (kt + 1 < nkt) {
            loadkv(st ^ 1, kt + 1);
            CP_WAIT(1);
        } else {
            CP_WAIT(0);
        }
        __syncthreads();

        const uint32_t kb = smb + QB + st * (2 * KVST);
        const uint32_t vb = kb + KVST;
        const int k0 = kt * 64;

        float s[8][4];
#pragma unroll
        for (int nn = 0; nn < 8; nn++)
#pragma unroll
            for (int i = 0; i < 4; i++) s[nn][i] = 0.f;

#pragma unroll
        for (int kg = 0; kg < 8; kg++) {
            uint32_t a[4];
            ldsm_x4(a, qoff + kg * 32);
#pragma unroll
            for (int p = 0; p < 4; p++) {
                uint32_t b[4];
                ldsm_x4(b, kb + koff + p * (16 * ASTR * 2) + kg * 32);
                mma_f16(s[2 * p],     a[0], a[1], a[2], a[3], b[0], b[1]);
                mma_f16(s[2 * p + 1], a[0], a[1], a[2], a[3], b[2], b[3]);
            }
        }

        if (k0 + 63 > row0) {
#pragma unroll
            for (int nn = 0; nn < 8; nn++) {
                int col = k0 + nn * 8 + 2 * t;
                if (col > row0)     s[nn][0] = -1e30f;
                if (col + 1 > row0) s[nn][1] = -1e30f;
                if (col > row0 + 8)     s[nn][2] = -1e30f;
                if (col + 1 > row0 + 8) s[nn][3] = -1e30f;
            }
        }

        float mx0 = -1e30f, mx1 = -1e30f;
#pragma unroll
        for (int nn = 0; nn < 8; nn++) {
            mx0 = fmaxf(mx0, fmaxf(s[nn][0], s[nn][1]));
            mx1 = fmaxf(mx1, fmaxf(s[nn][2], s[nn][3]));
        }
        mx0 = fmaxf(mx0, __shfl_xor_sync(0xffffffffu, mx0, 1));
        mx0 = fmaxf(mx0, __shfl_xor_sync(0xffffffffu, mx0, 2));
        mx1 = fmaxf(mx1, __shfl_xor_sync(0xffffffffu, mx1, 1));
        mx1 = fmaxf(mx1, __shfl_xor_sync(0xffffffffu, mx1, 2));

        float newm0 = fmaxf(m0, mx0);
        float newm1 = fmaxf(m1, mx1);
        float alpha0 = __expf(m0 - newm0);
        float alpha1 = __expf(m1 - newm1);
        m0 = newm0; m1 = newm1;

        float sum0 = 0.f, sum1 = 0.f;
#pragma unroll
        for (int nn = 0; nn < 8; nn++) {
            s[nn][0] = __expf(s[nn][0] - newm0);
            s[nn][1] = __expf(s[nn][1] - newm0);
            s[nn][2] = __expf(s[nn][2] - newm1);
            s[nn][3] = __expf(s[nn][3] - newm1);
            sum0 += s[nn][0] + s[nn][1];
            sum1 += s[nn][2] + s[nn][3];
        }
        sum0 += __shfl_xor_sync(0xffffffffu, sum0, 1);
        sum0 += __shfl_xor_sync(0xffffffffu, sum0, 2);
        sum1 += __shfl_xor_sync(0xffffffffu, sum1, 1);
        sum1 += __shfl_xor_sync(0xffffffffu, sum1, 2);
        l0 = l0 * alpha0 + sum0;
        l1 = l1 * alpha1 + sum1;

#pragma unroll
        for (int dd = 0; dd < 16; dd++) {
            o[dd][0] *= alpha0; o[dd][1] *= alpha0;
            o[dd][2] *= alpha1; o[dd][3] *= alpha1;
        }

#pragma unroll
        for (int kg = 0; kg < 4; kg++) {
            uint32_t a0 = pack_h2(s[2 * kg][0],     s[2 * kg][1]);
            uint32_t a1 = pack_h2(s[2 * kg][2],     s[2 * kg][3]);
            uint32_t a2 = pack_h2(s[2 * kg + 1][0], s[2 * kg + 1][1]);
            uint32_t a3 = pack_h2(s[2 * kg + 1][2], s[2 * kg + 1][3]);
            const uint32_t vkg = vb + voff + kg * (16 * ASTR * 2);
#pragma unroll
            for (int p = 0; p < 8; p++) {
                uint32_t b[4];
                ldsm_x4_t(b, vkg + p * 32);
                mma_f16(o[2 * p],     a0, a1, a2, a3, b[0], b[1]);
                mma_f16(o[2 * p + 1], a0, a1, a2, a3, b[2], b[3]);
            }
        }
        __syncthreads();
    }

    float inv0 = 1.f / l0;
    float inv1 = 1.f / l1;
    size_t r0 = (rowbase + row0) * HDIM + hoff;
    size_t r1 = r0 + 8 * HDIM;
#pragma unroll
    for (int dd = 0; dd < 16; dd++) {
        int col = dd * 8 + 2 * t;
        *(__half2*)(g_C + r0 + col) =
            __floats2half2_rn(o[dd][0] * inv0, o[dd][1] * inv0);
        *(__half2*)(g_C + r1 + col) =
            __floats2half2_rn(o[dd][2] * inv1, o[dd][3] * inv1);
    }
}

// ---------------------------------------------------------------------------
// kernel_launch
// Inputs: 0=X 1=position_ids 2=mask(unused,causal) 3=Wq 4=Wk 5=Wv 6=Wo 7=bo
// ---------------------------------------------------------------------------
extern "C" void kernel_launch(void* const* d_in, const int* in_sizes, int n_in,
                              void* d_out, int out_size)
{
    const float* X   = (const float*)d_in[0];
    const int*   pos = (const int*)d_in[1];
    const float* Wq  = (const float*)d_in[3];
    const float* Wk  = (const float*)d_in[4];
    const float* Wv  = (const float*)d_in[5];
    const float* Wo  = (const float*)d_in[6];
    const float* bo  = (const float*)d_in[7];
    float* out = (float*)d_out;

    cudaFuncSetAttribute(qkv_gemm_kernel,
                         cudaFuncAttributeMaxDynamicSharedMemorySize,
                         GEMM_SMEM_BYTES);
    cudaFuncSetAttribute(out_gemm_kernel,
                         cudaFuncAttributeMaxDynamicSharedMemorySize,
                         GEMM_SMEM_BYTES);
    cudaFuncSetAttribute(attn_kernel,
                         cudaFuncAttributeMaxDynamicSharedMemorySize,
                         ATT_SMEM_BYTES);

    __half *dX, *dWq, *dWk, *dWv, *dWo;
    cudaGetSymbolAddress((void**)&dX,  g_X);
    cudaGetSymbolAddress((void**)&dWq, g_Wq);
    cudaGetSymbolAddress((void**)&dWk, g_Wk);
    cudaGetSymbolAddress((void**)&dWv, g_Wv);
    cudaGetSymbolAddress((void**)&dWo, g_Wo);

    const float rs = 0.08838834764831845f;   // 1/sqrt(128)
    int nx8 = MROWS * HDIM / 8;               // 1048576
    int nw8 = HDIM * HDIM / 8;                // 524288
    dim3 g_cvt(nx8 / 256, 5);
    cvt_all_kernel<<<g_cvt, 256>>>(X, Wq, Wk, Wv, Wo,
                                   dX, dWq, dWk, dWv, dWo, nx8, nw8, rs);

    dim3 g_qkv(HDIM / 128, MROWS / 128, 3);
    qkv_gemm_kernel<<<g_qkv, 128, GEMM_SMEM_BYTES>>>();

    int rope_threads = MROWS * NH * 32;
    rope_kernel<<<(rope_threads + 255) / 256, 256>>>(pos);

    dim3 g_att(S_LEN / 128, NH, NB);
    attn_kernel<<<g_att, 256, ATT_SMEM_BYTES>>>();

    dim3 g_out(HDIM / 128, MROWS / 128);
    out_gemm_kernel<<<g_out, 128, GEMM_SMEM_BYTES>>>(bo, out);
}

// round 17
// speedup vs baseline: 1.1142x; 1.1142x over previous
#include <cuda_runtime.h>
#include <cuda_fp16.h>
#include <math.h>
#include <stdint.h>

#define S_LEN 2048
#define HDIM  2048
#define NB    2
#define NH    16
#define DH    128
#define MROWS (NB * S_LEN)   // 4096

__device__ __half g_Q[MROWS * HDIM];
__device__ __half g_K[MROWS * HDIM];
__device__ __half g_V[MROWS * HDIM];
__device__ __half g_C[MROWS * HDIM];
__device__ __half g_X[MROWS * HDIM];
__device__ __half g_Wq[HDIM * HDIM];   // pre-scaled log2(e)/sqrt(dh)
__device__ __half g_Wk[HDIM * HDIM];
__device__ __half g_Wv[HDIM * HDIM];
__device__ __half g_Wo[HDIM * HDIM];

// ---------------------------------------------------------------------------
// fp16 MMA m16n8k16 + ldmatrix helpers
// ---------------------------------------------------------------------------
__device__ __forceinline__ void mma_f16(float* c, uint32_t a0, uint32_t a1,
                                        uint32_t a2, uint32_t a3,
                                        uint32_t b0, uint32_t b1)
{
    asm("mma.sync.aligned.m16n8k16.row.col.f32.f16.f16.f32 "
        "{%0,%1,%2,%3}, {%4,%5,%6,%7}, {%8,%9}, {%0,%1,%2,%3};"
        : "+f"(c[0]), "+f"(c[1]), "+f"(c[2]), "+f"(c[3])
        : "r"(a0), "r"(a1), "r"(a2), "r"(a3), "r"(b0), "r"(b1));
}

__device__ __forceinline__ void ldsm_x4(uint32_t* r, uint32_t addr)
{
    asm volatile("ldmatrix.sync.aligned.m8n8.x4.shared.b16 {%0,%1,%2,%3}, [%4];"
                 : "=r"(r[0]), "=r"(r[1]), "=r"(r[2]), "=r"(r[3]) : "r"(addr));
}

__device__ __forceinline__ void ldsm_x4_t(uint32_t* r, uint32_t addr)
{
    asm volatile(
        "ldmatrix.sync.aligned.m8n8.x4.trans.shared.b16 {%0,%1,%2,%3}, [%4];"
        : "=r"(r[0]), "=r"(r[1]), "=r"(r[2]), "=r"(r[3]) : "r"(addr));
}

__device__ __forceinline__ uint32_t pack_h2(float lo, float hi)
{
    __half2 h = __floats2half2_rn(lo, hi);
    return *(uint32_t*)&h;
}

__device__ __forceinline__ void cp_async16(uint32_t saddr, const void* g)
{
    asm volatile("cp.async.cg.shared.global [%0], [%1], 16;"
                 :: "r"(saddr), "l"(g));
}
#define CP_COMMIT() asm volatile("cp.async.commit_group;")
#define CP_WAIT(N)  asm volatile("cp.async.wait_group %0;" :: "n"(N))

// ---------------------------------------------------------------------------
// fp32 -> fp16 pre-rounding copy: y=0 -> X, y=1..4 -> Wq,Wk,Wv,Wo (fused)
// ---------------------------------------------------------------------------
__global__ void cvt_all_kernel(const float* __restrict__ X,
                               const float* __restrict__ Wq,
                               const float* __restrict__ Wk,
                               const float* __restrict__ Wv,
                               const float* __restrict__ Wo,
                               __half* __restrict__ dX,
                               __half* __restrict__ dWq,
                               __half* __restrict__ dWk,
                               __half* __restrict__ dWv,
                               __half* __restrict__ dWo,
                               int nx8, int nw8, float rs)
{
    int i = blockIdx.x * 256 + threadIdx.x;
    int y = blockIdx.y;
    int n8 = (y == 0) ? nx8 : nw8;
    if (i >= n8) return;
    const float* src = (y == 0) ? X : (y == 1) ? Wq : (y == 2) ? Wk
                     : (y == 3) ? Wv : Wo;
    __half* dst = (y == 0) ? dX : (y == 1) ? dWq : (y == 2) ? dWk
                : (y == 3) ? dWv : dWo;
    float scale = (y == 1) ? rs : 1.f;
    float4 v0 = ((const float4*)src)[2 * i];
    float4 v1 = ((const float4*)src)[2 * i + 1];
    uint4 o;
    o.x = pack_h2(v0.x * scale, v0.y * scale);
    o.y = pack_h2(v0.z * scale, v0.w * scale);
    o.z = pack_h2(v1.x * scale, v1.y * scale);
    o.w = pack_h2(v1.z * scale, v1.w * scale);
    ((uint4*)dst)[i] = o;
}

// ---------------------------------------------------------------------------
// fp16 GEMM (R15-proven): CTA 128x128, 4 warps, BK=32, ldmatrix frags,
// rows padded 80B, FOUR cp.async stages, wait_group 2, 2 CTAs/SM.
// ---------------------------------------------------------------------------
#define GK 2048
#define STAGE_B 10240                     // 128 rows * 80 bytes
#define NSTG 4
#define GEMM_SMEM_BYTES (NSTG * 2 * STAGE_B) // 81920

template <bool TOHALF, bool HASBIAS>
__device__ __forceinline__ void gemm_f16_body(const __half* __restrict__ A,
                                              const __half* __restrict__ B,
                                              const float* __restrict__ bias,
                                              void* __restrict__ Cout)
{
    extern __shared__ __align__(16) char smem[];
    uint32_t sbase = (uint32_t)__cvta_generic_to_shared(smem);

    const int tid    = threadIdx.x;
    const int lane   = tid & 31;
    const int wid    = tid >> 5;
    const int warp_m = wid >> 1;
    const int warp_n = wid & 1;
    const int g      = lane >> 2;
    const int t      = lane & 3;
    const int bm     = blockIdx.y * 128;
    const int bn     = blockIdx.x * 128;

    const int tr = tid >> 2;
    const int tc = tid & 3;
    const __half* gA = A + (size_t)(bm + tr) * GK + tc * 8;
    const __half* gB = B + (size_t)(bn + tr) * GK + tc * 8;
    const uint32_t dst0 = tr * 80 + tc * 16;

    auto issue = [&](int stage) {
        uint32_t da = sbase + stage * STAGE_B + dst0;
        uint32_t db = da + NSTG * STAGE_B;
#pragma unroll
        for (int it = 0; it < 4; it++)
            cp_async16(da + it * 32 * 80, gA + (size_t)it * 32 * GK);
#pragma unroll
        for (int it = 0; it < 4; it++)
            cp_async16(db + it * 32 * 80, gB + (size_t)it * 32 * GK);
        gA += 32;
        gB += 32;
        CP_COMMIT();
    };

    issue(0);
    issue(1);
    issue(2);

    float acc[4][8][4];
#pragma unroll
    for (int mt = 0; mt < 4; mt++)
#pragma unroll
        for (int nt = 0; nt < 8; nt++)
#pragma unroll
            for (int i = 0; i < 4; i++) acc[mt][nt][i] = 0.f;

    const uint32_t aoff =
        ((warp_m * 64 + (lane & 15)) * 40 + (lane >> 4) * 8) * 2;
    const uint32_t boff =
        ((warp_n * 64 + (lane & 7) + (lane >> 4) * 8) * 40 +
         ((lane >> 3) & 1) * 8) * 2;

    const int nk = GK / 32;   // 64
    for (int kt = 0; kt < nk; kt++) {
        if (kt < nk - 2)      { CP_WAIT(2); }
        else if (kt < nk - 1) { CP_WAIT(1); }
        else                  { CP_WAIT(0); }
        __syncthreads();
        if (kt + 3 < nk) issue((kt + 3) % NSTG);

        const uint32_t sAst = sbase + (kt % NSTG) * STAGE_B;
        const uint32_t sBst = sAst + NSTG * STAGE_B;

#pragma unroll
        for (int kg = 0; kg < 2; kg++) {
            uint32_t a[4][4], b[4][4];
#pragma unroll
            for (int mt = 0; mt < 4; mt++)
                ldsm_x4(a[mt], sAst + aoff + mt * 1280 + kg * 32);
#pragma unroll
            for (int p = 0; p < 4; p++)
                ldsm_x4(b[p], sBst + boff + p * 1280 + kg * 32);
#pragma unroll
            for (int mt = 0; mt < 4; mt++)
#pragma unroll
                for (int p = 0; p < 4; p++) {
                    mma_f16(acc[mt][2 * p], a[mt][0], a[mt][1], a[mt][2],
                            a[mt][3], b[p][0], b[p][1]);
                    mma_f16(acc[mt][2 * p + 1], a[mt][0], a[mt][1], a[mt][2],
                            a[mt][3], b[p][2], b[p][3]);
                }
        }
    }

#pragma unroll
    for (int mt = 0; mt < 4; mt++) {
        int row = bm + warp_m * 64 + mt * 16 + g;
#pragma unroll
        for (int nt = 0; nt < 8; nt++) {
            int col = bn + warp_n * 64 + nt * 8 + 2 * t;
            if (TOHALF) {
                __half* C = (__half*)Cout;
                *(__half2*)(C + (size_t)row * HDIM + col) =
                    __floats2half2_rn(acc[mt][nt][0], acc[mt][nt][1]);
                *(__half2*)(C + (size_t)(row + 8) * HDIM + col) =
                    __floats2half2_rn(acc[mt][nt][2], acc[mt][nt][3]);
            } else {
                float* C = (float*)Cout;
                float b0 = 0.f, b1 = 0.f;
                if (HASBIAS) { b0 = bias[col]; b1 = bias[col + 1]; }
                *(float2*)(C + (size_t)row * HDIM + col) =
                    make_float2(acc[mt][nt][0] + b0, acc[mt][nt][1] + b1);
                *(float2*)(C + (size_t)(row + 8) * HDIM + col) =
                    make_float2(acc[mt][nt][2] + b0, acc[mt][nt][3] + b1);
            }
        }
    }
}

__global__ void __launch_bounds__(128, 2) qkv_gemm_kernel()
{
    const __half* B = (blockIdx.z == 0) ? g_Wq : (blockIdx.z == 1) ? g_Wk : g_Wv;
    __half* C       = (blockIdx.z == 0) ? g_Q  : (blockIdx.z == 1) ? g_K  : g_V;
    gemm_f16_body<true, false>(g_X, B, nullptr, C);
}

__global__ void __launch_bounds__(128, 2) out_gemm_kernel(
    const float* __restrict__ bo, float* __restrict__ out)
{
    gemm_f16_body<false, true>(g_C, g_Wo, bo, out);
}

// ---------------------------------------------------------------------------
// RoPE in-place on g_Q, g_K — vectorized half2 (2 adjacent d per thread).
// ---------------------------------------------------------------------------
__global__ void rope_kernel(const int* __restrict__ pos_ids)
{
    int idx = blockIdx.x * 256 + threadIdx.x;
    if (idx >= MROWS * NH * 32) return;
    int d2 = idx & 31;
    int h  = (idx >> 5) & 15;
    int m  = idx >> 9;
    int s  = m & (S_LEN - 1);

    float p = (float)pos_ids[s];
    int d = 2 * d2;
    float th0 = expf(-0.14391156531392624f * (float)d);
    float th1 = expf(-0.14391156531392624f * (float)(d + 1));
    float sn0, cs0, sn1, cs1;
    sincosf(p * th0, &sn0, &cs0);
    sincosf(p * th1, &sn1, &cs1);

    size_t base = (size_t)m * HDIM + h * DH + d;
    float2 q1 = __half22float2(*(__half2*)(g_Q + base));
    float2 q2 = __half22float2(*(__half2*)(g_Q + base + 64));
    *(__half2*)(g_Q + base) =
        __floats2half2_rn(q1.x * cs0 - q2.x * sn0, q1.y * cs1 - q2.y * sn1);
    *(__half2*)(g_Q + base + 64) =
        __floats2half2_rn(q1.x * sn0 + q2.x * cs0, q1.y * sn1 + q2.y * cs1);
    float2 k1 = __half22float2(*(__half2*)(g_K + base));
    float2 k2 = __half22float2(*(__half2*)(g_K + base + 64));
    *(__half2*)(g_K + base) =
        __floats2half2_rn(k1.x * cs0 - k2.x * sn0, k1.y * cs1 - k2.y * sn1);
    *(__half2*)(g_K + base + 64) =
        __floats2half2_rn(k1.x * sn0 + k2.x * cs0, k1.y * sn1 + k2.y * cs1);
}

// ---------------------------------------------------------------------------
// fp16 flash attention: R11 pipeline (2 barriers/tile), DIAGONAL-FIRST tile
// order (kt descending) so the running max stabilizes immediately ->
// alpha==1 rescale skip on most tiles. Softmax in log2 domain (Q carries
// log2e/sqrt(dh)), exp2f throughout.
// ---------------------------------------------------------------------------
#define ASTR 136
#define QB   (128 * ASTR * 2)
#define KVST (64 * ASTR * 2)
#define ATT_SMEM_BYTES (QB + 2 * 2 * KVST)   // 104448

__global__ void __launch_bounds__(256, 2) attn_kernel()
{
    extern __shared__ __align__(16) __half smh[];
    __half* Qs = smh;

    const int tid  = threadIdx.x;
    const int lane = tid & 31;
    const int w    = tid >> 5;
    const int g    = lane >> 2;
    const int t    = lane & 3;
    const int qt   = (gridDim.x - 1) - blockIdx.x;   // heavy tiles first
    const int h    = blockIdx.y;
    const int n    = blockIdx.z;
    const int q0   = qt * 128;

    const size_t rowbase = (size_t)n * S_LEN;
    const size_t hoff    = (size_t)h * DH;

    const uint32_t smb = (uint32_t)__cvta_generic_to_shared(smh);

    const uint32_t qoff =
        smb + ((w * 16 + (lane & 15)) * ASTR + (lane >> 4) * 8) * 2;
    const uint32_t koff =
        (((lane & 7) + (lane >> 4) * 8) * ASTR + ((lane >> 3) & 1) * 8) * 2;
    const uint32_t voff =
        ((lane & 15) * ASTR + (lane >> 4) * 8) * 2;

    const int lr = tid >> 2;
    const int lc = tid & 3;
    auto loadkv = [&](int st, int kt) {
        int k0 = kt * 64;
        uint32_t kb = smb + QB + st * (2 * KVST);
        uint32_t vb = kb + KVST;
#pragma unroll
        for (int it = 0; it < 4; it++) {
            int c = lc * 4 + it;
            size_t gg = (rowbase + k0 + lr) * HDIM + hoff + c * 8;
            cp_async16(kb + (lr * ASTR + c * 8) * 2, g_K + gg);
            cp_async16(vb + (lr * ASTR + c * 8) * 2, g_V + gg);
        }
        CP_COMMIT();
    };

#pragma unroll
    for (int it = 0; it < 8; it++) {
        int id = tid + it * 256;
        int r  = id >> 4;
        int c  = id & 15;
        *(uint4*)&Qs[r * ASTR + c * 8] =
            *(const uint4*)(g_Q + (rowbase + q0 + r) * HDIM + hoff + c * 8);
    }

    float o[16][4];
#pragma unroll
    for (int dd = 0; dd < 16; dd++)
#pragma unroll
        for (int i = 0; i < 4; i++) o[dd][i] = 0.f;
    float m0 = -1e30f, m1 = -1e30f, l0 = 0.f, l1 = 0.f;

    const int row0 = q0 + w * 16 + g;
    const int nkt  = 2 * (qt + 1);

    // Diagonal-first: iterate tiles kt = nkt-1 .. 0 (it = 0 .. nkt-1)
    loadkv(0, nkt - 1);

    for (int it = 0; it < nkt; it++) {
        const int kt = nkt - 1 - it;
        const int st = it & 1;
        if (it + 1 < nkt) {
            loadkv(st ^ 1, kt - 1);
            CP_WAIT(1);
        } else {
            CP_WAIT(0);
        }
        __syncthreads();

        const uint32_t kb = smb + QB + st * (2 * KVST);
        const uint32_t vb = kb + KVST;
        const int k0 = kt * 64;

        float s[8][4];
#pragma unroll
        for (int nn = 0; nn < 8; nn++)
#pragma unroll
            for (int i = 0; i < 4; i++) s[nn][i] = 0.f;

#pragma unroll
        for (int kg = 0; kg < 8; kg++) {
            uint32_t a[4];
            ldsm_x4(a, qoff + kg * 32);
#pragma unroll
            for (int p = 0; p < 4; p++) {
                uint32_t b[4];
                ldsm_x4(b, kb + koff + p * (16 * ASTR * 2) + kg * 32);
                mma_f16(s[2 * p],     a[0], a[1], a[2], a[3], b[0], b[1]);
                mma_f16(s[2 * p + 1], a[0], a[1], a[2], a[3], b[2], b[3]);
            }
        }

        if (k0 + 63 > row0) {
#pragma unroll
            for (int nn = 0; nn < 8; nn++) {
                int col = k0 + nn * 8 + 2 * t;
                if (col > row0)     s[nn][0] = -1e30f;
                if (col + 1 > row0) s[nn][1] = -1e30f;
                if (col > row0 + 8)     s[nn][2] = -1e30f;
                if (col + 1 > row0 + 8) s[nn][3] = -1e30f;
            }
        }

        float mx0 = -1e30f, mx1 = -1e30f;
#pragma unroll
        for (int nn = 0; nn < 8; nn++) {
            mx0 = fmaxf(mx0, fmaxf(s[nn][0], s[nn][1]));
            mx1 = fmaxf(mx1, fmaxf(s[nn][2], s[nn][3]));
        }
        mx0 = fmaxf(mx0, __shfl_xor_sync(0xffffffffu, mx0, 1));
        mx0 = fmaxf(mx0, __shfl_xor_sync(0xffffffffu, mx0, 2));
        mx1 = fmaxf(mx1, __shfl_xor_sync(0xffffffffu, mx1, 1));
        mx1 = fmaxf(mx1, __shfl_xor_sync(0xffffffffu, mx1, 2));

        float newm0 = fmaxf(m0, mx0);
        float newm1 = fmaxf(m1, mx1);
        bool norescale = (newm0 == m0) && (newm1 == m1);
        if (!__all_sync(0xffffffffu, norescale)) {
            float alpha0 = exp2f(m0 - newm0);
            float alpha1 = exp2f(m1 - newm1);
            l0 *= alpha0;
            l1 *= alpha1;
#pragma unroll
            for (int dd = 0; dd < 16; dd++) {
                o[dd][0] *= alpha0; o[dd][1] *= alpha0;
                o[dd][2] *= alpha1; o[dd][3] *= alpha1;
            }
        }
        m0 = newm0; m1 = newm1;

        float sum0 = 0.f, sum1 = 0.f;
#pragma unroll
        for (int nn = 0; nn < 8; nn++) {
            s[nn][0] = exp2f(s[nn][0] - newm0);
            s[nn][1] = exp2f(s[nn][1] - newm0);
            s[nn][2] = exp2f(s[nn][2] - newm1);
            s[nn][3] = exp2f(s[nn][3] - newm1);
            sum0 += s[nn][0] + s[nn][1];
            sum1 += s[nn][2] + s[nn][3];
        }
        sum0 += __shfl_xor_sync(0xffffffffu, sum0, 1);
        sum0 += __shfl_xor_sync(0xffffffffu, sum0, 2);
        sum1 += __shfl_xor_sync(0xffffffffu, sum1, 1);
        sum1 += __shfl_xor_sync(0xffffffffu, sum1, 2);
        l0 += sum0;
        l1 += sum1;

#pragma unroll
        for (int kg = 0; kg < 4; kg++) {
            uint32_t a0 = pack_h2(s[2 * kg][0],     s[2 * kg][1]);
            uint32_t a1 = pack_h2(s[2 * kg][2],     s[2 * kg][3]);
            uint32_t a2 = pack_h2(s[2 * kg + 1][0], s[2 * kg + 1][1]);
            uint32_t a3 = pack_h2(s[2 * kg + 1][2], s[2 * kg + 1][3]);
            const uint32_t vkg = vb + voff + kg * (16 * ASTR * 2);
#pragma unroll
            for (int p = 0; p < 8; p++) {
                uint32_t b[4];
                ldsm_x4_t(b, vkg + p * 32);
                mma_f16(o[2 * p],     a0, a1, a2, a3, b[0], b[1]);
                mma_f16(o[2 * p + 1], a0, a1, a2, a3, b[2], b[3]);
            }
        }
        __syncthreads();
    }

    float inv0 = 1.f / l0;
    float inv1 = 1.f / l1;
    size_t r0 = (rowbase + row0) * HDIM + hoff;
    size_t r1 = r0 + 8 * HDIM;
#pragma unroll
    for (int dd = 0; dd < 16; dd++) {
        int col = dd * 8 + 2 * t;
        *(__half2*)(g_C + r0 + col) =
            __floats2half2_rn(o[dd][0] * inv0, o[dd][1] * inv0);
        *(__half2*)(g_C + r1 + col) =
            __floats2half2_rn(o[dd][2] * inv1, o[dd][3] * inv1);
    }
}

// ---------------------------------------------------------------------------
// kernel_launch
// Inputs: 0=X 1=position_ids 2=mask(unused,causal) 3=Wq 4=Wk 5=Wv 6=Wo 7=bo
// ---------------------------------------------------------------------------
extern "C" void kernel_launch(void* const* d_in, const int* in_sizes, int n_in,
                              void* d_out, int out_size)
{
    const float* X   = (const float*)d_in[0];
    const int*   pos = (const int*)d_in[1];
    const float* Wq  = (const float*)d_in[3];
    const float* Wk  = (const float*)d_in[4];
    const float* Wv  = (const float*)d_in[5];
    const float* Wo  = (const float*)d_in[6];
    const float* bo  = (const float*)d_in[7];
    float* out = (float*)d_out;

    cudaFuncSetAttribute(qkv_gemm_kernel,
                         cudaFuncAttributeMaxDynamicSharedMemorySize,
                         GEMM_SMEM_BYTES);
    cudaFuncSetAttribute(out_gemm_kernel,
                         cudaFuncAttributeMaxDynamicSharedMemorySize,
                         GEMM_SMEM_BYTES);
    cudaFuncSetAttribute(attn_kernel,
                         cudaFuncAttributeMaxDynamicSharedMemorySize,
                         ATT_SMEM_BYTES);

    __half *dX, *dWq, *dWk, *dWv, *dWo;
    cudaGetSymbolAddress((void**)&dX,  g_X);
    cudaGetSymbolAddress((void**)&dWq, g_Wq);
    cudaGetSymbolAddress((void**)&dWk, g_Wk);
    cudaGetSymbolAddress((void**)&dWv, g_Wv);
    cudaGetSymbolAddress((void**)&dWo, g_Wo);

    // log2(e) / sqrt(128): softmax runs in log2 domain
    const float rs = 0.08838834764831845f * 1.4426950408889634f;
    int nx8 = MROWS * HDIM / 8;
    int nw8 = HDIM * HDIM / 8;
    dim3 g_cvt(nx8 / 256, 5);
    cvt_all_kernel<<<g_cvt, 256>>>(X, Wq, Wk, Wv, Wo,
                                   dX, dWq, dWk, dWv, dWo, nx8, nw8, rs);

    dim3 g_qkv(HDIM / 128, MROWS / 128, 3);
    qkv_gemm_kernel<<<g_qkv, 128, GEMM_SMEM_BYTES>>>();

    int rope_threads = MROWS * NH * 32;
    rope_kernel<<<(rope_threads + 255) / 256, 256>>>(pos);

    dim3 g_att(S_LEN / 128, NH, NB);
    attn_kernel<<<g_att, 256, ATT_SMEM_BYTES>>>();

    dim3 g_out(HDIM / 128, MROWS / 128);
    out_gemm_kernel<<<g_out, 128, GEMM_SMEM_BYTES>>>(bo, out);
}